// round 14
// baseline (speedup 1.0000x reference)
#include <cuda_runtime.h>
#include <cuda_bf16.h>
#include <math.h>
#include <stdint.h>

#define H 256
#define BM 64
#define MAXN 500000
#define MAXB 1024

// scratch (device globals: allocation-free rule)
__device__ float g_e[MAXN];           // exp(score) per node (shift-free)
__device__ float g_den[MAXB];         // softmax denominator per segment
__device__ int   g_seg[MAXB + 1];
__device__ int   g_is64;
// W1 prepacked for MMA B operand: [kt 0..15][tig 0..3][col 0..255] ->
// uint2 = ( bf16x2(rows kt*16+2tig, +1), bf16x2(rows kt*16+2tig+8, +9) )
__device__ uint2 g_Wpk2[16 * 1024];

// ---------------- helpers ----------------

__device__ __forceinline__ uint32_t bf2_pack(float a, float b) {
    __nv_bfloat162 h = __floats2bfloat162_rn(a, b);  // .x = a (low half)
    return *reinterpret_cast<uint32_t*>(&h);
}

__device__ __forceinline__ void mma_bf16(float c[4], const uint32_t a[4],
                                         uint32_t b0, uint32_t b1) {
    asm volatile(
        "mma.sync.aligned.m16n8k16.row.col.f32.bf16.bf16.f32 "
        "{%0,%1,%2,%3}, {%4,%5,%6,%7}, {%8,%9}, {%0,%1,%2,%3};\n"
        : "+f"(c[0]), "+f"(c[1]), "+f"(c[2]), "+f"(c[3])
        : "r"(a[0]), "r"(a[1]), "r"(a[2]), "r"(a[3]), "r"(b0), "r"(b1));
}

__device__ __forceinline__ float tanh_fast(float z) {
    float e = __expf(2.0f * z);
    return 1.0f - 2.0f / (e + 1.0f);
}

// ---------------- kernel 0: detect batch dtype (int32 vs int64) ----------------
__global__ void detect_kernel(const void* __restrict__ batch, int n, int B) {
    const long long* b64 = (const long long*)batch;
    int i0 = n / 2 - 1; if (i0 < 0) i0 = 0;
    int i1 = n / 4;     if (i1 >= n / 2) i1 = i0;
    long long v0 = b64[i0];
    long long v1 = b64[i1];
    g_is64 = (v0 >= 0 && v0 < B && v1 >= 0 && v1 < B) ? 1 : 0;
}

__device__ __forceinline__ int read_batch(const void* p, int i, int is64) {
    return is64 ? (int)((const long long*)p)[i] : ((const int*)p)[i];
}

// ---------------- kernel 0b: init denominators; prepack W1 ----------------
__global__ void init_kernel(int B) {
    int i = blockIdx.x * 256 + threadIdx.x;
    if (i < B) g_den[i] = 0.0f;
}

// blockIdx.x = kt*4 + tig (64 blocks), threadIdx.x = col (256)
__global__ void prep_kernel(const float* __restrict__ W1) {
    int kt  = blockIdx.x >> 2;
    int tig = blockIdx.x & 3;
    int col = threadIdx.x;
    int r0  = kt * 16 + 2 * tig;       // kpair tig
    int r1  = kt * 16 + 2 * tig + 8;   // kpair tig+4
    uint32_t lo = bf2_pack(W1[r0 * H + col], W1[(r0 + 1) * H + col]);
    uint32_t hi = bf2_pack(W1[r1 * H + col], W1[(r1 + 1) * H + col]);
    g_Wpk2[kt * 1024 + tig * 256 + col] = make_uint2(lo, hi);
}

// ---------------- kernel 1: segment boundaries ----------------
__global__ void seg_kernel(const void* __restrict__ batch, int n, int B) {
    int i = blockIdx.x * blockDim.x + threadIdx.x;
    if (i >= n) return;
    int is64 = g_is64;
    int b = read_batch(batch, i, is64);
    b = b < 0 ? 0 : (b >= B ? B - 1 : b);
    if (i == 0) {
        for (int bb = 0; bb <= b; ++bb) g_seg[bb] = 0;
    } else {
        int pb = read_batch(batch, i - 1, is64);
        pb = pb < 0 ? 0 : (pb >= B ? B - 1 : pb);
        if (pb != b)
            for (int bb = pb + 1; bb <= b; ++bb) g_seg[bb] = i;
    }
    if (i == n - 1) {
        for (int bb = b + 1; bb <= B; ++bb) g_seg[bb] = n;
    }
}

// ---------------- kernel 2: attention scores -> exp + denom ----------------
// s[i] = tanh(x[i,:] @ W1 + b1) @ W2  (b2 dropped: softmax shift-invariant)
// 1-term bf16 (X and W rounded): output rel err ~1e-5, threshold 1e-3.
// BARRIER-FREE mainloop: X tile resident in smem (packed once, 1 sync);
// B read straight from L2 (g_Wpk2 is 128KB, permanently hot; warpM pairs
// and the co-resident CTA dedup in L1). Warps fully independent.
// X smem [row][136 words]: kt block at row*136+kt*8, pair p at slot
//   (p<4 ? 2p : 2(p-4)+1). A read = uint2 at row*136+kt*8+2tig ->
//   (pair tig, pair tig+4). Banks/phase: 8*gid+2*tig all distinct.
__global__ void __launch_bounds__(256, 2)
score_kernel(const float* __restrict__ x, const void* __restrict__ batch,
             const float* __restrict__ b1, const float* __restrict__ W2,
             int n) {
    __shared__ __align__(16) uint32_t Xs[BM * 136];
    __shared__ float b1s[H];
    __shared__ float w2s[H];
    __shared__ float ssh[BM * 4];

    const int tid   = threadIdx.x;
    const int lane  = tid & 31;
    const int warp  = tid >> 5;
    const int warpM = warp >> 2;   // 0..1
    const int warpN = warp & 3;    // 0..3
    const int gid   = lane >> 2;   // 0..7
    const int tig   = lane & 3;    // 0..3
    const long long m0 = (long long)blockIdx.x * BM;

    b1s[tid] = b1[tid];
    w2s[tid] = W2[tid];

    // ---- stage X tile (hi bf16 pairs), once ----
    {
        const int xr = tid >> 2;     // 0..63
        const int xc = tid & 3;      // 0..3
        const bool xok = (m0 + xr < n);
        const float* xrow = x + (m0 + xr) * (long long)H;
        const int s0tab[4] = {0, 4, 1, 5};
        #pragma unroll
        for (int j = 0; j < 16; ++j) {
            int f  = xc + 4 * j;          // float4 index 0..63 along row
            int kt = f >> 2;
            int c  = f & 3;
            float4 v = make_float4(0.f, 0.f, 0.f, 0.f);
            if (xok) v = *(const float4*)(xrow + 4 * f);
            int base = xr * 136 + kt * 8 + s0tab[c];
            Xs[base]     = bf2_pack(v.x, v.y);
            Xs[base + 2] = bf2_pack(v.z, v.w);
        }
    }
    __syncthreads();   // the ONLY pre-epilogue barrier

    // ---- barrier-free mainloop ----
    const uint2* __restrict__ Wp = g_Wpk2 + tig * 256 + warpN * 64 + gid;

    float acc[2][8][4];
    #pragma unroll
    for (int mt = 0; mt < 2; ++mt)
        #pragma unroll
        for (int nt = 0; nt < 8; ++nt)
            #pragma unroll
            for (int c = 0; c < 4; ++c) acc[mt][nt][c] = 0.0f;

    #pragma unroll
    for (int kt = 0; kt < 16; ++kt) {
        uint32_t ah[2][4];
        #pragma unroll
        for (int mt = 0; mt < 2; ++mt) {
            int r0 = warpM * 32 + mt * 16 + gid;
            uint2 qa = *(const uint2*)&Xs[r0 * 136 + kt * 8 + 2 * tig];
            uint2 qb = *(const uint2*)&Xs[(r0 + 8) * 136 + kt * 8 + 2 * tig];
            ah[mt][0] = qa.x; ah[mt][2] = qa.y;
            ah[mt][1] = qb.x; ah[mt][3] = qb.y;
        }
        #pragma unroll
        for (int nt = 0; nt < 8; ++nt) {
            uint2 bp = __ldg(&Wp[kt * 1024 + nt * 8]);  // (kpair tig, tig+4)
            mma_bf16(acc[0][nt], ah[0], bp.x, bp.y);
            mma_bf16(acc[1][nt], ah[1], bp.x, bp.y);
        }
    }

    // epilogue: s_row = sum_cols tanh(z + b1) * w2
    #pragma unroll
    for (int mt = 0; mt < 2; ++mt) {
        float p0v = 0.0f, p1v = 0.0f;
        #pragma unroll
        for (int nt = 0; nt < 8; ++nt) {
            int c0 = warpN * 64 + nt * 8 + 2 * tig;
            float w0 = w2s[c0], w1v = w2s[c0 + 1];
            float e0 = b1s[c0], e1 = b1s[c0 + 1];
            p0v += w0 * tanh_fast(acc[mt][nt][0] + e0) + w1v * tanh_fast(acc[mt][nt][1] + e1);
            p1v += w0 * tanh_fast(acc[mt][nt][2] + e0) + w1v * tanh_fast(acc[mt][nt][3] + e1);
        }
        p0v += __shfl_xor_sync(0xffffffffu, p0v, 1);
        p0v += __shfl_xor_sync(0xffffffffu, p0v, 2);
        p1v += __shfl_xor_sync(0xffffffffu, p1v, 1);
        p1v += __shfl_xor_sync(0xffffffffu, p1v, 2);
        if (tig == 0) {
            int row0 = warpM * 32 + mt * 16 + gid;
            ssh[row0 * 4 + warpN]       = p0v;
            ssh[(row0 + 8) * 4 + warpN] = p1v;
        }
    }
    __syncthreads();
    if (tid < BM && m0 + tid < n) {
        float s = ssh[tid * 4] + ssh[tid * 4 + 1] + ssh[tid * 4 + 2] + ssh[tid * 4 + 3];
        float e = __expf(s);
        g_e[m0 + tid] = e;
        int b = read_batch(batch, (int)(m0 + tid), g_is64);
        atomicAdd(&g_den[b], e);
    }
}

// ---------------- kernel 3: fused mean/max/attn pooling ----------------
__global__ void pool_kernel(const float* __restrict__ x, float* __restrict__ out, int B) {
    int b = blockIdx.x;
    int start = g_seg[b], end = g_seg[b + 1];
    int len = end - start;
    float* orow = out + (long long)b * (3 * H);

    if (len <= 0) {
        for (int j = threadIdx.x; j < 3 * H; j += 256) orow[j] = 0.0f;
        return;
    }

    int r = threadIdx.x >> 6;   // 0..3
    int c = threadIdx.x & 63;   // 0..63 (float4 col)

    float4 sum = make_float4(0.f, 0.f, 0.f, 0.f);
    float4 att = make_float4(0.f, 0.f, 0.f, 0.f);
    float4 mx  = make_float4(-INFINITY, -INFINITY, -INFINITY, -INFINITY);

    for (int i = start + r; i < end; i += 4) {
        float ei = g_e[i];
        float4 xv = *(const float4*)(x + (long long)i * H + c * 4);
        sum.x += xv.x; sum.y += xv.y; sum.z += xv.z; sum.w += xv.w;
        mx.x = fmaxf(mx.x, xv.x); mx.y = fmaxf(mx.y, xv.y);
        mx.z = fmaxf(mx.z, xv.z); mx.w = fmaxf(mx.w, xv.w);
        att.x += ei * xv.x; att.y += ei * xv.y;
        att.z += ei * xv.z; att.w += ei * xv.w;
    }

    __shared__ float4 shsum[4][64];
    __shared__ float4 shmax[4][64];
    __shared__ float4 shatt[4][64];
    shsum[r][c] = sum; shmax[r][c] = mx; shatt[r][c] = att;
    __syncthreads();

    if (r == 0) {
        #pragma unroll
        for (int rr = 1; rr < 4; ++rr) {
            float4 s2 = shsum[rr][c], m2 = shmax[rr][c], a2 = shatt[rr][c];
            sum.x += s2.x; sum.y += s2.y; sum.z += s2.z; sum.w += s2.w;
            mx.x = fmaxf(mx.x, m2.x); mx.y = fmaxf(mx.y, m2.y);
            mx.z = fmaxf(mx.z, m2.z); mx.w = fmaxf(mx.w, m2.w);
            att.x += a2.x; att.y += a2.y; att.z += a2.z; att.w += a2.w;
        }
        float invc = 1.0f / (float)len;
        float invd = 1.0f / g_den[b];
        float4 mean = make_float4(sum.x * invc, sum.y * invc, sum.z * invc, sum.w * invc);
        float4 attn = make_float4(att.x * invd, att.y * invd, att.z * invd, att.w * invd);
        *(float4*)(orow + c * 4)         = mean;
        *(float4*)(orow + H + c * 4)     = mx;
        *(float4*)(orow + 2 * H + c * 4) = attn;
    }
}

// ---------------- launch (score at ncu index 3) ----------------
extern "C" void kernel_launch(void* const* d_in, const int* in_sizes, int n_in,
                              void* d_out, int out_size) {
    const float* x     = (const float*)d_in[0];
    const void*  batch = d_in[1];
    const float* W1    = (const float*)d_in[2];
    const float* b1    = (const float*)d_in[3];
    const float* W2    = (const float*)d_in[4];
    float*       out   = (float*)d_out;

    int n = in_sizes[1];
    int B = out_size / (3 * H);

    detect_kernel<<<1, 1>>>(batch, n, B);
    prep_kernel<<<64, 256>>>(W1);
    init_kernel<<<(B + 255) / 256, 256>>>(B);
    score_kernel<<<(n + BM - 1) / BM, 256>>>(x, batch, b1, W2, n);
    seg_kernel<<<(n + 255) / 256, 256>>>(batch, n, B);
    pool_kernel<<<B, 256>>>(x, out, B);
}

// round 15
// speedup vs baseline: 1.0900x; 1.0900x over previous
#include <cuda_runtime.h>
#include <cuda_bf16.h>
#include <math.h>
#include <stdint.h>

#define H 256
#define BM 64
#define MAXN 500000
#define MAXB 1024

// scratch (device globals: allocation-free rule)
__device__ float g_e[MAXN];           // exp(score) per node (shift-free)
__device__ float g_den[MAXB];         // softmax denominator per segment
__device__ int   g_seg[MAXB + 1];
__device__ int   g_is64;
// W1 prepacked for MMA B operand: [kt 0..15][tig 0..3][col 0..255] ->
// uint2 = ( bf16x2(rows kt*16+2tig, +1), bf16x2(rows kt*16+2tig+8, +9) )
__device__ uint2 g_Wpk2[16 * 1024];

// ---------------- helpers ----------------

__device__ __forceinline__ uint32_t bf2_pack(float a, float b) {
    __nv_bfloat162 h = __floats2bfloat162_rn(a, b);  // .x = a (low half)
    return *reinterpret_cast<uint32_t*>(&h);
}

__device__ __forceinline__ void mma_bf16(float c[4], const uint32_t a[4],
                                         uint32_t b0, uint32_t b1) {
    asm volatile(
        "mma.sync.aligned.m16n8k16.row.col.f32.bf16.bf16.f32 "
        "{%0,%1,%2,%3}, {%4,%5,%6,%7}, {%8,%9}, {%0,%1,%2,%3};\n"
        : "+f"(c[0]), "+f"(c[1]), "+f"(c[2]), "+f"(c[3])
        : "r"(a[0]), "r"(a[1]), "r"(a[2]), "r"(a[3]), "r"(b0), "r"(b1));
}

__device__ __forceinline__ float tanh_fast(float z) {
    float e = __expf(2.0f * z);
    return 1.0f - 2.0f / (e + 1.0f);
}

// ---------------- kernel 0: detect batch dtype (int32 vs int64) ----------------
__global__ void detect_kernel(const void* __restrict__ batch, int n, int B) {
    const long long* b64 = (const long long*)batch;
    int i0 = n / 2 - 1; if (i0 < 0) i0 = 0;
    int i1 = n / 4;     if (i1 >= n / 2) i1 = i0;
    long long v0 = b64[i0];
    long long v1 = b64[i1];
    g_is64 = (v0 >= 0 && v0 < B && v1 >= 0 && v1 < B) ? 1 : 0;
}

__device__ __forceinline__ int read_batch(const void* p, int i, int is64) {
    return is64 ? (int)((const long long*)p)[i] : ((const int*)p)[i];
}

// ---------------- kernel 0b: init denominators; prepack W1 ----------------
__global__ void init_kernel(int B) {
    int i = blockIdx.x * 256 + threadIdx.x;
    if (i < B) g_den[i] = 0.0f;
}

// blockIdx.x = kt*4 + tig (64 blocks), threadIdx.x = col (256)
__global__ void prep_kernel(const float* __restrict__ W1) {
    int kt  = blockIdx.x >> 2;
    int tig = blockIdx.x & 3;
    int col = threadIdx.x;
    int r0  = kt * 16 + 2 * tig;       // kpair tig
    int r1  = kt * 16 + 2 * tig + 8;   // kpair tig+4
    uint32_t lo = bf2_pack(W1[r0 * H + col], W1[(r0 + 1) * H + col]);
    uint32_t hi = bf2_pack(W1[r1 * H + col], W1[(r1 + 1) * H + col]);
    g_Wpk2[kt * 1024 + tig * 256 + col] = make_uint2(lo, hi);
}

// ---------------- kernel 1: segment boundaries ----------------
__global__ void seg_kernel(const void* __restrict__ batch, int n, int B) {
    int i = blockIdx.x * blockDim.x + threadIdx.x;
    if (i >= n) return;
    int is64 = g_is64;
    int b = read_batch(batch, i, is64);
    b = b < 0 ? 0 : (b >= B ? B - 1 : b);
    if (i == 0) {
        for (int bb = 0; bb <= b; ++bb) g_seg[bb] = 0;
    } else {
        int pb = read_batch(batch, i - 1, is64);
        pb = pb < 0 ? 0 : (pb >= B ? B - 1 : pb);
        if (pb != b)
            for (int bb = pb + 1; bb <= b; ++bb) g_seg[bb] = i;
    }
    if (i == n - 1) {
        for (int bb = b + 1; bb <= B; ++bb) g_seg[bb] = n;
    }
}

// ---------------- kernel 2: attention scores -> exp + denom ----------------
// s[i] = tanh(x[i,:] @ W1 + b1) @ W2  (b2 dropped: softmax shift-invariant)
// 1-term bf16 (X and W rounded): output rel err ~1e-5, threshold 1e-3.
// OCCUPANCY build: N split into 2 halves -> warp tile 32x32, 32 acc regs,
// 3 CTAs/SM (24 warps). Resident X in smem (1 sync), barrier-free mainloop,
// W direct from L2-hot g_Wpk2.
// X smem [row][136 words]: kt block at row*136+kt*8, pair p at slot
//   (p<4 ? 2p : 2(p-4)+1). A read = uint2 at row*136+kt*8+2tig.
__global__ void __launch_bounds__(256, 3)
score_kernel(const float* __restrict__ x, const void* __restrict__ batch,
             const float* __restrict__ b1, const float* __restrict__ W2,
             int n) {
    __shared__ __align__(16) uint32_t Xs[BM * 136];
    __shared__ float b1s[H];
    __shared__ float w2s[H];
    __shared__ float ssh[BM * 4];

    const int tid   = threadIdx.x;
    const int lane  = tid & 31;
    const int warp  = tid >> 5;
    const int warpM = warp >> 2;   // 0..1
    const int warpN = warp & 3;    // 0..3
    const int gid   = lane >> 2;   // 0..7
    const int tig   = lane & 3;    // 0..3
    const long long m0 = (long long)blockIdx.x * BM;

    b1s[tid] = b1[tid];
    w2s[tid] = W2[tid];

    // ---- stage X tile (hi bf16 pairs), once ----
    {
        const int xr = tid >> 2;     // 0..63
        const int xc = tid & 3;      // 0..3
        const bool xok = (m0 + xr < n);
        const float* xrow = x + (m0 + xr) * (long long)H;
        const int s0tab[4] = {0, 4, 1, 5};
        #pragma unroll
        for (int j = 0; j < 16; ++j) {
            int f  = xc + 4 * j;          // float4 index 0..63 along row
            int kt = f >> 2;
            int c  = f & 3;
            float4 v = make_float4(0.f, 0.f, 0.f, 0.f);
            if (xok) v = *(const float4*)(xrow + 4 * f);
            int base = xr * 136 + kt * 8 + s0tab[c];
            Xs[base]     = bf2_pack(v.x, v.y);
            Xs[base + 2] = bf2_pack(v.z, v.w);
        }
    }
    __syncthreads();   // the ONLY pre-epilogue barrier

    // ---- barrier-free mainloop over two N-halves ----
    float sp[2][2];    // running tanh-dot partials [mt][p0/p1]
    sp[0][0] = sp[0][1] = sp[1][0] = sp[1][1] = 0.0f;

    #pragma unroll
    for (int nh = 0; nh < 2; ++nh) {
        const uint2* __restrict__ Wp =
            g_Wpk2 + tig * 256 + nh * 128 + warpN * 32 + gid;

        float acc[2][4][4];
        #pragma unroll
        for (int mt = 0; mt < 2; ++mt)
            #pragma unroll
            for (int nt = 0; nt < 4; ++nt)
                #pragma unroll
                for (int c = 0; c < 4; ++c) acc[mt][nt][c] = 0.0f;

        #pragma unroll
        for (int kt = 0; kt < 16; ++kt) {
            uint32_t ah[2][4];
            #pragma unroll
            for (int mt = 0; mt < 2; ++mt) {
                int r0 = warpM * 32 + mt * 16 + gid;
                uint2 qa = *(const uint2*)&Xs[r0 * 136 + kt * 8 + 2 * tig];
                uint2 qb = *(const uint2*)&Xs[(r0 + 8) * 136 + kt * 8 + 2 * tig];
                ah[mt][0] = qa.x; ah[mt][2] = qa.y;
                ah[mt][1] = qb.x; ah[mt][3] = qb.y;
            }
            #pragma unroll
            for (int nt = 0; nt < 4; ++nt) {
                uint2 bp = __ldg(&Wp[kt * 1024 + nt * 8]);  // (kpair tig, tig+4)
                mma_bf16(acc[0][nt], ah[0], bp.x, bp.y);
                mma_bf16(acc[1][nt], ah[1], bp.x, bp.y);
            }
        }

        // per-half epilogue: fold tanh-dot into running partials
        #pragma unroll
        for (int mt = 0; mt < 2; ++mt) {
            #pragma unroll
            for (int nt = 0; nt < 4; ++nt) {
                int c0 = nh * 128 + warpN * 32 + nt * 8 + 2 * tig;
                float w0 = w2s[c0], w1v = w2s[c0 + 1];
                float e0 = b1s[c0], e1 = b1s[c0 + 1];
                sp[mt][0] += w0 * tanh_fast(acc[mt][nt][0] + e0)
                           + w1v * tanh_fast(acc[mt][nt][1] + e1);
                sp[mt][1] += w0 * tanh_fast(acc[mt][nt][2] + e0)
                           + w1v * tanh_fast(acc[mt][nt][3] + e1);
            }
        }
    }

    // reduce across tig lanes, write per-warpN slots
    #pragma unroll
    for (int mt = 0; mt < 2; ++mt) {
        float p0v = sp[mt][0], p1v = sp[mt][1];
        p0v += __shfl_xor_sync(0xffffffffu, p0v, 1);
        p0v += __shfl_xor_sync(0xffffffffu, p0v, 2);
        p1v += __shfl_xor_sync(0xffffffffu, p1v, 1);
        p1v += __shfl_xor_sync(0xffffffffu, p1v, 2);
        if (tig == 0) {
            int row0 = warpM * 32 + mt * 16 + gid;
            ssh[row0 * 4 + warpN]       = p0v;
            ssh[(row0 + 8) * 4 + warpN] = p1v;
        }
    }
    __syncthreads();
    if (tid < BM && m0 + tid < n) {
        float s = ssh[tid * 4] + ssh[tid * 4 + 1] + ssh[tid * 4 + 2] + ssh[tid * 4 + 3];
        float e = __expf(s);
        g_e[m0 + tid] = e;
        int b = read_batch(batch, (int)(m0 + tid), g_is64);
        atomicAdd(&g_den[b], e);
    }
}

// ---------------- kernel 3: fused mean/max/attn pooling ----------------
__global__ void pool_kernel(const float* __restrict__ x, float* __restrict__ out, int B) {
    int b = blockIdx.x;
    int start = g_seg[b], end = g_seg[b + 1];
    int len = end - start;
    float* orow = out + (long long)b * (3 * H);

    if (len <= 0) {
        for (int j = threadIdx.x; j < 3 * H; j += 256) orow[j] = 0.0f;
        return;
    }

    int r = threadIdx.x >> 6;   // 0..3
    int c = threadIdx.x & 63;   // 0..63 (float4 col)

    float4 sum = make_float4(0.f, 0.f, 0.f, 0.f);
    float4 att = make_float4(0.f, 0.f, 0.f, 0.f);
    float4 mx  = make_float4(-INFINITY, -INFINITY, -INFINITY, -INFINITY);

    for (int i = start + r; i < end; i += 4) {
        float ei = g_e[i];
        float4 xv = *(const float4*)(x + (long long)i * H + c * 4);
        sum.x += xv.x; sum.y += xv.y; sum.z += xv.z; sum.w += xv.w;
        mx.x = fmaxf(mx.x, xv.x); mx.y = fmaxf(mx.y, xv.y);
        mx.z = fmaxf(mx.z, xv.z); mx.w = fmaxf(mx.w, xv.w);
        att.x += ei * xv.x; att.y += ei * xv.y;
        att.z += ei * xv.z; att.w += ei * xv.w;
    }

    __shared__ float4 shsum[4][64];
    __shared__ float4 shmax[4][64];
    __shared__ float4 shatt[4][64];
    shsum[r][c] = sum; shmax[r][c] = mx; shatt[r][c] = att;
    __syncthreads();

    if (r == 0) {
        #pragma unroll
        for (int rr = 1; rr < 4; ++rr) {
            float4 s2 = shsum[rr][c], m2 = shmax[rr][c], a2 = shatt[rr][c];
            sum.x += s2.x; sum.y += s2.y; sum.z += s2.z; sum.w += s2.w;
            mx.x = fmaxf(mx.x, m2.x); mx.y = fmaxf(mx.y, m2.y);
            mx.z = fmaxf(mx.z, m2.z); mx.w = fmaxf(mx.w, m2.w);
            att.x += a2.x; att.y += a2.y; att.z += a2.z; att.w += a2.w;
        }
        float invc = 1.0f / (float)len;
        float invd = 1.0f / g_den[b];
        float4 mean = make_float4(sum.x * invc, sum.y * invc, sum.z * invc, sum.w * invc);
        float4 attn = make_float4(att.x * invd, att.y * invd, att.z * invd, att.w * invd);
        *(float4*)(orow + c * 4)         = mean;
        *(float4*)(orow + H + c * 4)     = mx;
        *(float4*)(orow + 2 * H + c * 4) = attn;
    }
}

// ---------------- launch (score at ncu index 3) ----------------
extern "C" void kernel_launch(void* const* d_in, const int* in_sizes, int n_in,
                              void* d_out, int out_size) {
    const float* x     = (const float*)d_in[0];
    const void*  batch = d_in[1];
    const float* W1    = (const float*)d_in[2];
    const float* b1    = (const float*)d_in[3];
    const float* W2    = (const float*)d_in[4];
    float*       out   = (float*)d_out;

    int n = in_sizes[1];
    int B = out_size / (3 * H);

    detect_kernel<<<1, 1>>>(batch, n, B);
    prep_kernel<<<64, 256>>>(W1);
    init_kernel<<<(B + 255) / 256, 256>>>(B);
    score_kernel<<<(n + BM - 1) / BM, 256>>>(x, batch, b1, W2, n);
    seg_kernel<<<(n + 255) / 256, 256>>>(batch, n, B);
    pool_kernel<<<B, 256>>>(x, out, B);
}

// round 16
// speedup vs baseline: 1.2025x; 1.1032x over previous
#include <cuda_runtime.h>
#include <cuda_bf16.h>
#include <math.h>
#include <stdint.h>

#define H 256
#define BM 64
#define MAXN 500000
#define MAXB 1024

// scratch (device globals: allocation-free rule)
__device__ float g_e[MAXN];           // exp(score) per node (shift-free)
__device__ float g_den[MAXB];         // softmax denominator per segment
__device__ int   g_seg[MAXB + 1];
__device__ int   g_is64;
// W1 prepacked, lane-coalesced for LDG.128:
// g_W4[(kt*16 + bp)*32 + lane] = uint4 covering n-tiles (2bp, 2bp+1):
//   .x = bf16x2(W1[kt*16+2tig][c0], W1[kt*16+2tig+1][c0])   (kpair tig)
//   .y = bf16x2(W1[kt*16+2tig+8][c0], W1[kt*16+2tig+9][c0]) (kpair tig+4)
//   .z/.w = same for c1 = c0+8,  where c0 = 16*bp + gid.
__device__ uint4 g_W4[16 * 16 * 32];

// ---------------- helpers ----------------

__device__ __forceinline__ uint32_t bf2_pack(float a, float b) {
    __nv_bfloat162 h = __floats2bfloat162_rn(a, b);  // .x = a (low half)
    return *reinterpret_cast<uint32_t*>(&h);
}

__device__ __forceinline__ void mma_bf16(float c[4], const uint32_t a[4],
                                         uint32_t b0, uint32_t b1) {
    asm volatile(
        "mma.sync.aligned.m16n8k16.row.col.f32.bf16.bf16.f32 "
        "{%0,%1,%2,%3}, {%4,%5,%6,%7}, {%8,%9}, {%0,%1,%2,%3};\n"
        : "+f"(c[0]), "+f"(c[1]), "+f"(c[2]), "+f"(c[3])
        : "r"(a[0]), "r"(a[1]), "r"(a[2]), "r"(a[3]), "r"(b0), "r"(b1));
}

__device__ __forceinline__ float tanh_fast(float z) {
    float e = __expf(2.0f * z);
    return 1.0f - 2.0f / (e + 1.0f);
}

// ---------------- kernel 0: detect batch dtype (int32 vs int64) ----------------
__global__ void detect_kernel(const void* __restrict__ batch, int n, int B) {
    const long long* b64 = (const long long*)batch;
    int i0 = n / 2 - 1; if (i0 < 0) i0 = 0;
    int i1 = n / 4;     if (i1 >= n / 2) i1 = i0;
    long long v0 = b64[i0];
    long long v1 = b64[i1];
    g_is64 = (v0 >= 0 && v0 < B && v1 >= 0 && v1 < B) ? 1 : 0;
}

__device__ __forceinline__ int read_batch(const void* p, int i, int is64) {
    return is64 ? (int)((const long long*)p)[i] : ((const int*)p)[i];
}

// ---------------- kernel 0b: init denominators; prepack W1 ----------------
__global__ void init_kernel(int B) {
    int i = blockIdx.x * 256 + threadIdx.x;
    if (i < B) g_den[i] = 0.0f;
}

// 8192 uint4 entries; 32 blocks x 256 threads
__global__ void prep_kernel(const float* __restrict__ W1) {
    int idx  = blockIdx.x * 256 + threadIdx.x;   // 0..8191
    int lane = idx & 31;
    int bp   = (idx >> 5) & 15;
    int kt   = idx >> 9;
    int gid  = lane >> 2;
    int tig  = lane & 3;
    int r0 = kt * 16 + 2 * tig;
    int r1 = r0 + 8;
    int c0 = 16 * bp + gid;
    int c1 = c0 + 8;
    uint4 u;
    u.x = bf2_pack(W1[r0 * H + c0], W1[(r0 + 1) * H + c0]);
    u.y = bf2_pack(W1[r1 * H + c0], W1[(r1 + 1) * H + c0]);
    u.z = bf2_pack(W1[r0 * H + c1], W1[(r0 + 1) * H + c1]);
    u.w = bf2_pack(W1[r1 * H + c1], W1[(r1 + 1) * H + c1]);
    g_W4[idx] = u;
}

// ---------------- kernel 1: segment boundaries ----------------
__global__ void seg_kernel(const void* __restrict__ batch, int n, int B) {
    int i = blockIdx.x * blockDim.x + threadIdx.x;
    if (i >= n) return;
    int is64 = g_is64;
    int b = read_batch(batch, i, is64);
    b = b < 0 ? 0 : (b >= B ? B - 1 : b);
    if (i == 0) {
        for (int bb = 0; bb <= b; ++bb) g_seg[bb] = 0;
    } else {
        int pb = read_batch(batch, i - 1, is64);
        pb = pb < 0 ? 0 : (pb >= B ? B - 1 : pb);
        if (pb != b)
            for (int bb = pb + 1; bb <= b; ++bb) g_seg[bb] = i;
    }
    if (i == n - 1) {
        for (int bb = b + 1; bb <= B; ++bb) g_seg[bb] = n;
    }
}

// ---------------- kernel 2: attention scores -> exp + denom ----------------
// s[i] = tanh(x[i,:] @ W1 + b1) @ W2  (b2 dropped: softmax shift-invariant)
// 1-term bf16 (X and W rounded): output rel err ~1e-5, threshold 1e-3.
// 3 CTAs/SM (N-split, 32 acc regs). Barrier-free mainloop; resident X.
// W via lane-coalesced LDG.128 (2 per kt per half: 8 lines/kt vs 32 before).
__global__ void __launch_bounds__(256, 3)
score_kernel(const float* __restrict__ x, const void* __restrict__ batch,
             const float* __restrict__ b1, const float* __restrict__ W2,
             int n) {
    __shared__ __align__(16) uint32_t Xs[BM * 136];
    __shared__ float b1s[H];
    __shared__ float w2s[H];
    __shared__ float ssh[BM * 4];

    const int tid   = threadIdx.x;
    const int lane  = tid & 31;
    const int warp  = tid >> 5;
    const int warpM = warp >> 2;   // 0..1
    const int warpN = warp & 3;    // 0..3
    const int gid   = lane >> 2;   // 0..7
    const int tig   = lane & 3;    // 0..3
    const long long m0 = (long long)blockIdx.x * BM;

    b1s[tid] = b1[tid];
    w2s[tid] = W2[tid];

    // ---- stage X tile (hi bf16 pairs), once ----
    {
        const int xr = tid >> 2;     // 0..63
        const int xc = tid & 3;      // 0..3
        const bool xok = (m0 + xr < n);
        const float* xrow = x + (m0 + xr) * (long long)H;
        const int s0tab[4] = {0, 4, 1, 5};
        #pragma unroll
        for (int j = 0; j < 16; ++j) {
            int f  = xc + 4 * j;          // float4 index 0..63 along row
            int kt = f >> 2;
            int c  = f & 3;
            float4 v = make_float4(0.f, 0.f, 0.f, 0.f);
            if (xok) v = *(const float4*)(xrow + 4 * f);
            int base = xr * 136 + kt * 8 + s0tab[c];
            Xs[base]     = bf2_pack(v.x, v.y);
            Xs[base + 2] = bf2_pack(v.z, v.w);
        }
    }
    __syncthreads();   // the ONLY pre-epilogue barrier

    // ---- barrier-free mainloop over two N-halves ----
    float sp[2][2];    // running tanh-dot partials [mt][p0/p1]
    sp[0][0] = sp[0][1] = sp[1][0] = sp[1][1] = 0.0f;

    #pragma unroll
    for (int nh = 0; nh < 2; ++nh) {
        // block-pair base for this warp's 32-col slice within half nh
        const int base_bp = nh * 8 + warpN * 2;
        const uint4* __restrict__ Wp = g_W4 + base_bp * 32 + lane;

        float acc[2][4][4];
        #pragma unroll
        for (int mt = 0; mt < 2; ++mt)
            #pragma unroll
            for (int nt = 0; nt < 4; ++nt)
                #pragma unroll
                for (int c = 0; c < 4; ++c) acc[mt][nt][c] = 0.0f;

        #pragma unroll
        for (int kt = 0; kt < 16; ++kt) {
            uint32_t ah[2][4];
            #pragma unroll
            for (int mt = 0; mt < 2; ++mt) {
                int r0 = warpM * 32 + mt * 16 + gid;
                uint2 qa = *(const uint2*)&Xs[r0 * 136 + kt * 8 + 2 * tig];
                uint2 qb = *(const uint2*)&Xs[(r0 + 8) * 136 + kt * 8 + 2 * tig];
                ah[mt][0] = qa.x; ah[mt][2] = qa.y;
                ah[mt][1] = qb.x; ah[mt][3] = qb.y;
            }
            uint4 wa = __ldg(&Wp[kt * 512]);        // n-tiles 0,1 of slice
            uint4 wb = __ldg(&Wp[kt * 512 + 32]);   // n-tiles 2,3 of slice
            mma_bf16(acc[0][0], ah[0], wa.x, wa.y);
            mma_bf16(acc[1][0], ah[1], wa.x, wa.y);
            mma_bf16(acc[0][1], ah[0], wa.z, wa.w);
            mma_bf16(acc[1][1], ah[1], wa.z, wa.w);
            mma_bf16(acc[0][2], ah[0], wb.x, wb.y);
            mma_bf16(acc[1][2], ah[1], wb.x, wb.y);
            mma_bf16(acc[0][3], ah[0], wb.z, wb.w);
            mma_bf16(acc[1][3], ah[1], wb.z, wb.w);
        }

        // per-half epilogue: fold tanh-dot into running partials
        #pragma unroll
        for (int mt = 0; mt < 2; ++mt) {
            #pragma unroll
            for (int nt = 0; nt < 4; ++nt) {
                int c0 = nh * 128 + warpN * 32 + nt * 8 + 2 * tig;
                float w0 = w2s[c0], w1v = w2s[c0 + 1];
                float e0 = b1s[c0], e1 = b1s[c0 + 1];
                sp[mt][0] += w0 * tanh_fast(acc[mt][nt][0] + e0)
                           + w1v * tanh_fast(acc[mt][nt][1] + e1);
                sp[mt][1] += w0 * tanh_fast(acc[mt][nt][2] + e0)
                           + w1v * tanh_fast(acc[mt][nt][3] + e1);
            }
        }
    }

    // reduce across tig lanes, write per-warpN slots
    #pragma unroll
    for (int mt = 0; mt < 2; ++mt) {
        float p0v = sp[mt][0], p1v = sp[mt][1];
        p0v += __shfl_xor_sync(0xffffffffu, p0v, 1);
        p0v += __shfl_xor_sync(0xffffffffu, p0v, 2);
        p1v += __shfl_xor_sync(0xffffffffu, p1v, 1);
        p1v += __shfl_xor_sync(0xffffffffu, p1v, 2);
        if (tig == 0) {
            int row0 = warpM * 32 + mt * 16 + gid;
            ssh[row0 * 4 + warpN]       = p0v;
            ssh[(row0 + 8) * 4 + warpN] = p1v;
        }
    }
    __syncthreads();
    if (tid < BM && m0 + tid < n) {
        float s = ssh[tid * 4] + ssh[tid * 4 + 1] + ssh[tid * 4 + 2] + ssh[tid * 4 + 3];
        float e = __expf(s);
        g_e[m0 + tid] = e;
        int b = read_batch(batch, (int)(m0 + tid), g_is64);
        atomicAdd(&g_den[b], e);
    }
}

// ---------------- kernel 3: fused mean/max/attn pooling ----------------
__global__ void pool_kernel(const float* __restrict__ x, float* __restrict__ out, int B) {
    int b = blockIdx.x;
    int start = g_seg[b], end = g_seg[b + 1];
    int len = end - start;
    float* orow = out + (long long)b * (3 * H);

    if (len <= 0) {
        for (int j = threadIdx.x; j < 3 * H; j += 256) orow[j] = 0.0f;
        return;
    }

    int r = threadIdx.x >> 6;   // 0..3
    int c = threadIdx.x & 63;   // 0..63 (float4 col)

    float4 sum = make_float4(0.f, 0.f, 0.f, 0.f);
    float4 att = make_float4(0.f, 0.f, 0.f, 0.f);
    float4 mx  = make_float4(-INFINITY, -INFINITY, -INFINITY, -INFINITY);

    for (int i = start + r; i < end; i += 4) {
        float ei = g_e[i];
        float4 xv = *(const float4*)(x + (long long)i * H + c * 4);
        sum.x += xv.x; sum.y += xv.y; sum.z += xv.z; sum.w += xv.w;
        mx.x = fmaxf(mx.x, xv.x); mx.y = fmaxf(mx.y, xv.y);
        mx.z = fmaxf(mx.z, xv.z); mx.w = fmaxf(mx.w, xv.w);
        att.x += ei * xv.x; att.y += ei * xv.y;
        att.z += ei * xv.z; att.w += ei * xv.w;
    }

    __shared__ float4 shsum[4][64];
    __shared__ float4 shmax[4][64];
    __shared__ float4 shatt[4][64];
    shsum[r][c] = sum; shmax[r][c] = mx; shatt[r][c] = att;
    __syncthreads();

    if (r == 0) {
        #pragma unroll
        for (int rr = 1; rr < 4; ++rr) {
            float4 s2 = shsum[rr][c], m2 = shmax[rr][c], a2 = shatt[rr][c];
            sum.x += s2.x; sum.y += s2.y; sum.z += s2.z; sum.w += s2.w;
            mx.x = fmaxf(mx.x, m2.x); mx.y = fmaxf(mx.y, m2.y);
            mx.z = fmaxf(mx.z, m2.z); mx.w = fmaxf(mx.w, m2.w);
            att.x += a2.x; att.y += a2.y; att.z += a2.z; att.w += a2.w;
        }
        float invc = 1.0f / (float)len;
        float invd = 1.0f / g_den[b];
        float4 mean = make_float4(sum.x * invc, sum.y * invc, sum.z * invc, sum.w * invc);
        float4 attn = make_float4(att.x * invd, att.y * invd, att.z * invd, att.w * invd);
        *(float4*)(orow + c * 4)         = mean;
        *(float4*)(orow + H + c * 4)     = mx;
        *(float4*)(orow + 2 * H + c * 4) = attn;
    }
}

// ---------------- launch (score at ncu index 3) ----------------
extern "C" void kernel_launch(void* const* d_in, const int* in_sizes, int n_in,
                              void* d_out, int out_size) {
    const float* x     = (const float*)d_in[0];
    const void*  batch = d_in[1];
    const float* W1    = (const float*)d_in[2];
    const float* b1    = (const float*)d_in[3];
    const float* W2    = (const float*)d_in[4];
    float*       out   = (float*)d_out;

    int n = in_sizes[1];
    int B = out_size / (3 * H);

    detect_kernel<<<1, 1>>>(batch, n, B);
    prep_kernel<<<32, 256>>>(W1);
    init_kernel<<<(B + 255) / 256, 256>>>(B);
    score_kernel<<<(n + BM - 1) / BM, 256>>>(x, batch, b1, W2, n);
    seg_kernel<<<(n + 255) / 256, 256>>>(batch, n, B);
    pool_kernel<<<B, 256>>>(x, out, B);
}

// round 17
// speedup vs baseline: 1.2351x; 1.0271x over previous
#include <cuda_runtime.h>
#include <cuda_bf16.h>
#include <math.h>
#include <stdint.h>

#define H 256
#define BM 64
#define MAXN 500000
#define MAXB 1024

// scratch (device globals: allocation-free rule)
__device__ float g_e[MAXN];           // exp(score) per node (shift-free)
__device__ float g_den[MAXB];         // softmax denominator per segment
__device__ int   g_seg[MAXB + 1];
__device__ int   g_is64;
// W1 prepacked, lane-coalesced for LDG.128:
// g_W4[(kt*16 + bp)*32 + lane] = uint4 covering n-tiles (2bp, 2bp+1):
//   .x = bf16x2(W1[kt*16+2tig][c0], W1[kt*16+2tig+1][c0])   (kpair tig)
//   .y = bf16x2(W1[kt*16+2tig+8][c0], W1[kt*16+2tig+9][c0]) (kpair tig+4)
//   .z/.w = same for c1 = c0+8,  where c0 = 16*bp + gid.
__device__ uint4 g_W4[16 * 16 * 32];

// ---------------- helpers ----------------

__device__ __forceinline__ uint32_t bf2_pack(float a, float b) {
    __nv_bfloat162 h = __floats2bfloat162_rn(a, b);  // .x = a (low half)
    return *reinterpret_cast<uint32_t*>(&h);
}

__device__ __forceinline__ void mma_bf16(float c[4], const uint32_t a[4],
                                         uint32_t b0, uint32_t b1) {
    asm volatile(
        "mma.sync.aligned.m16n8k16.row.col.f32.bf16.bf16.f32 "
        "{%0,%1,%2,%3}, {%4,%5,%6,%7}, {%8,%9}, {%0,%1,%2,%3};\n"
        : "+f"(c[0]), "+f"(c[1]), "+f"(c[2]), "+f"(c[3])
        : "r"(a[0]), "r"(a[1]), "r"(a[2]), "r"(a[3]), "r"(b0), "r"(b1));
}

__device__ __forceinline__ float tanh_fast(float z) {
    float e = __expf(2.0f * z);
    return 1.0f - 2.0f / (e + 1.0f);
}

// ---------------- kernel 0: detect batch dtype (int32 vs int64) ----------------
__global__ void detect_kernel(const void* __restrict__ batch, int n, int B) {
    const long long* b64 = (const long long*)batch;
    int i0 = n / 2 - 1; if (i0 < 0) i0 = 0;
    int i1 = n / 4;     if (i1 >= n / 2) i1 = i0;
    long long v0 = b64[i0];
    long long v1 = b64[i1];
    g_is64 = (v0 >= 0 && v0 < B && v1 >= 0 && v1 < B) ? 1 : 0;
}

__device__ __forceinline__ int read_batch(const void* p, int i, int is64) {
    return is64 ? (int)((const long long*)p)[i] : ((const int*)p)[i];
}

// ---------------- kernel 0b: init denominators; prepack W1 ----------------
__global__ void init_kernel(int B) {
    int i = blockIdx.x * 256 + threadIdx.x;
    if (i < B) g_den[i] = 0.0f;
}

// 8192 uint4 entries; 32 blocks x 256 threads
__global__ void prep_kernel(const float* __restrict__ W1) {
    int idx  = blockIdx.x * 256 + threadIdx.x;   // 0..8191
    int lane = idx & 31;
    int bp   = (idx >> 5) & 15;
    int kt   = idx >> 9;
    int gid  = lane >> 2;
    int tig  = lane & 3;
    int r0 = kt * 16 + 2 * tig;
    int r1 = r0 + 8;
    int c0 = 16 * bp + gid;
    int c1 = c0 + 8;
    uint4 u;
    u.x = bf2_pack(W1[r0 * H + c0], W1[(r0 + 1) * H + c0]);
    u.y = bf2_pack(W1[r1 * H + c0], W1[(r1 + 1) * H + c0]);
    u.z = bf2_pack(W1[r0 * H + c1], W1[(r0 + 1) * H + c1]);
    u.w = bf2_pack(W1[r1 * H + c1], W1[(r1 + 1) * H + c1]);
    g_W4[idx] = u;
}

// ---------------- kernel 1: segment boundaries ----------------
__global__ void seg_kernel(const void* __restrict__ batch, int n, int B) {
    int i = blockIdx.x * blockDim.x + threadIdx.x;
    if (i >= n) return;
    int is64 = g_is64;
    int b = read_batch(batch, i, is64);
    b = b < 0 ? 0 : (b >= B ? B - 1 : b);
    if (i == 0) {
        for (int bb = 0; bb <= b; ++bb) g_seg[bb] = 0;
    } else {
        int pb = read_batch(batch, i - 1, is64);
        pb = pb < 0 ? 0 : (pb >= B ? B - 1 : pb);
        if (pb != b)
            for (int bb = pb + 1; bb <= b; ++bb) g_seg[bb] = i;
    }
    if (i == n - 1) {
        for (int bb = b + 1; bb <= B; ++bb) g_seg[bb] = n;
    }
}

// ---------------- kernel 2: attention scores -> exp + denom ----------------
// s[i] = tanh(x[i,:] @ W1 + b1) @ W2  (b2 dropped: softmax shift-invariant)
// 1-term bf16 (X and W rounded): output rel err ~1e-5, threshold 1e-3.
// 4 CTAs/SM (N split in quarters -> 16 acc regs, <=64 regs total).
// Barrier-free mainloop; resident X; W via lane-coalesced LDG.128.
__global__ void __launch_bounds__(256, 4)
score_kernel(const float* __restrict__ x, const void* __restrict__ batch,
             const float* __restrict__ b1, const float* __restrict__ W2,
             int n) {
    __shared__ __align__(16) uint32_t Xs[BM * 136];
    __shared__ float b1s[H];
    __shared__ float w2s[H];
    __shared__ float ssh[BM * 4];

    const int tid   = threadIdx.x;
    const int lane  = tid & 31;
    const int warp  = tid >> 5;
    const int warpM = warp >> 2;   // 0..1
    const int warpN = warp & 3;    // 0..3
    const int gid   = lane >> 2;   // 0..7
    const int tig   = lane & 3;    // 0..3
    const long long m0 = (long long)blockIdx.x * BM;

    b1s[tid] = b1[tid];
    w2s[tid] = W2[tid];

    // ---- stage X tile (hi bf16 pairs), once ----
    {
        const int xr = tid >> 2;     // 0..63
        const int xc = tid & 3;      // 0..3
        const bool xok = (m0 + xr < n);
        const float* xrow = x + (m0 + xr) * (long long)H;
        const int s0tab[4] = {0, 4, 1, 5};
        #pragma unroll
        for (int j = 0; j < 16; ++j) {
            int f  = xc + 4 * j;          // float4 index 0..63 along row
            int kt = f >> 2;
            int c  = f & 3;
            float4 v = make_float4(0.f, 0.f, 0.f, 0.f);
            if (xok) v = *(const float4*)(xrow + 4 * f);
            int base = xr * 136 + kt * 8 + s0tab[c];
            Xs[base]     = bf2_pack(v.x, v.y);
            Xs[base + 2] = bf2_pack(v.z, v.w);
        }
    }
    __syncthreads();   // the ONLY pre-epilogue barrier

    // ---- barrier-free mainloop over four N-quarters ----
    float sp[2][2];    // running tanh-dot partials [mt][p0/p1]
    sp[0][0] = sp[0][1] = sp[1][0] = sp[1][1] = 0.0f;

    #pragma unroll
    for (int nq = 0; nq < 4; ++nq) {
        // warp covers 16 cols = one bp entry per kt
        const uint4* __restrict__ Wp = g_W4 + (nq * 4 + warpN) * 32 + lane;

        float acc[2][2][4];
        #pragma unroll
        for (int mt = 0; mt < 2; ++mt)
            #pragma unroll
            for (int nt = 0; nt < 2; ++nt)
                #pragma unroll
                for (int c = 0; c < 4; ++c) acc[mt][nt][c] = 0.0f;

        #pragma unroll
        for (int kt = 0; kt < 16; ++kt) {
            uint32_t ah[2][4];
            #pragma unroll
            for (int mt = 0; mt < 2; ++mt) {
                int r0 = warpM * 32 + mt * 16 + gid;
                uint2 qa = *(const uint2*)&Xs[r0 * 136 + kt * 8 + 2 * tig];
                uint2 qb = *(const uint2*)&Xs[(r0 + 8) * 136 + kt * 8 + 2 * tig];
                ah[mt][0] = qa.x; ah[mt][2] = qa.y;
                ah[mt][1] = qb.x; ah[mt][3] = qb.y;
            }
            uint4 wa = __ldg(&Wp[kt * 512]);   // n-tiles 0,1 of 16-col slice
            mma_bf16(acc[0][0], ah[0], wa.x, wa.y);
            mma_bf16(acc[1][0], ah[1], wa.x, wa.y);
            mma_bf16(acc[0][1], ah[0], wa.z, wa.w);
            mma_bf16(acc[1][1], ah[1], wa.z, wa.w);
        }

        // per-quarter epilogue: fold tanh-dot into running partials
        #pragma unroll
        for (int mt = 0; mt < 2; ++mt) {
            #pragma unroll
            for (int nt = 0; nt < 2; ++nt) {
                int c0 = nq * 64 + warpN * 16 + nt * 8 + 2 * tig;
                float w0 = w2s[c0], w1v = w2s[c0 + 1];
                float e0 = b1s[c0], e1 = b1s[c0 + 1];
                sp[mt][0] += w0 * tanh_fast(acc[mt][nt][0] + e0)
                           + w1v * tanh_fast(acc[mt][nt][1] + e1);
                sp[mt][1] += w0 * tanh_fast(acc[mt][nt][2] + e0)
                           + w1v * tanh_fast(acc[mt][nt][3] + e1);
            }
        }
    }

    // reduce across tig lanes, write per-warpN slots
    #pragma unroll
    for (int mt = 0; mt < 2; ++mt) {
        float p0v = sp[mt][0], p1v = sp[mt][1];
        p0v += __shfl_xor_sync(0xffffffffu, p0v, 1);
        p0v += __shfl_xor_sync(0xffffffffu, p0v, 2);
        p1v += __shfl_xor_sync(0xffffffffu, p1v, 1);
        p1v += __shfl_xor_sync(0xffffffffu, p1v, 2);
        if (tig == 0) {
            int row0 = warpM * 32 + mt * 16 + gid;
            ssh[row0 * 4 + warpN]       = p0v;
            ssh[(row0 + 8) * 4 + warpN] = p1v;
        }
    }
    __syncthreads();
    if (tid < BM && m0 + tid < n) {
        float s = ssh[tid * 4] + ssh[tid * 4 + 1] + ssh[tid * 4 + 2] + ssh[tid * 4 + 3];
        float e = __expf(s);
        g_e[m0 + tid] = e;
        int b = read_batch(batch, (int)(m0 + tid), g_is64);
        atomicAdd(&g_den[b], e);
    }
}

// ---------------- kernel 3: fused mean/max/attn pooling ----------------
__global__ void pool_kernel(const float* __restrict__ x, float* __restrict__ out, int B) {
    int b = blockIdx.x;
    int start = g_seg[b], end = g_seg[b + 1];
    int len = end - start;
    float* orow = out + (long long)b * (3 * H);

    if (len <= 0) {
        for (int j = threadIdx.x; j < 3 * H; j += 256) orow[j] = 0.0f;
        return;
    }

    int r = threadIdx.x >> 6;   // 0..3
    int c = threadIdx.x & 63;   // 0..63 (float4 col)

    float4 sum = make_float4(0.f, 0.f, 0.f, 0.f);
    float4 att = make_float4(0.f, 0.f, 0.f, 0.f);
    float4 mx  = make_float4(-INFINITY, -INFINITY, -INFINITY, -INFINITY);

    for (int i = start + r; i < end; i += 4) {
        float ei = g_e[i];
        float4 xv = *(const float4*)(x + (long long)i * H + c * 4);
        sum.x += xv.x; sum.y += xv.y; sum.z += xv.z; sum.w += xv.w;
        mx.x = fmaxf(mx.x, xv.x); mx.y = fmaxf(mx.y, xv.y);
        mx.z = fmaxf(mx.z, xv.z); mx.w = fmaxf(mx.w, xv.w);
        att.x += ei * xv.x; att.y += ei * xv.y;
        att.z += ei * xv.z; att.w += ei * xv.w;
    }

    __shared__ float4 shsum[4][64];
    __shared__ float4 shmax[4][64];
    __shared__ float4 shatt[4][64];
    shsum[r][c] = sum; shmax[r][c] = mx; shatt[r][c] = att;
    __syncthreads();

    if (r == 0) {
        #pragma unroll
        for (int rr = 1; rr < 4; ++rr) {
            float4 s2 = shsum[rr][c], m2 = shmax[rr][c], a2 = shatt[rr][c];
            sum.x += s2.x; sum.y += s2.y; sum.z += s2.z; sum.w += s2.w;
            mx.x = fmaxf(mx.x, m2.x); mx.y = fmaxf(mx.y, m2.y);
            mx.z = fmaxf(mx.z, m2.z); mx.w = fmaxf(mx.w, m2.w);
            att.x += a2.x; att.y += a2.y; att.z += a2.z; att.w += a2.w;
        }
        float invc = 1.0f / (float)len;
        float invd = 1.0f / g_den[b];
        float4 mean = make_float4(sum.x * invc, sum.y * invc, sum.z * invc, sum.w * invc);
        float4 attn = make_float4(att.x * invd, att.y * invd, att.z * invd, att.w * invd);
        *(float4*)(orow + c * 4)         = mean;
        *(float4*)(orow + H + c * 4)     = mx;
        *(float4*)(orow + 2 * H + c * 4) = attn;
    }
}

// ---------------- launch (score at ncu index 3) ----------------
extern "C" void kernel_launch(void* const* d_in, const int* in_sizes, int n_in,
                              void* d_out, int out_size) {
    const float* x     = (const float*)d_in[0];
    const void*  batch = d_in[1];
    const float* W1    = (const float*)d_in[2];
    const float* b1    = (const float*)d_in[3];
    const float* W2    = (const float*)d_in[4];
    float*       out   = (float*)d_out;

    int n = in_sizes[1];
    int B = out_size / (3 * H);

    detect_kernel<<<1, 1>>>(batch, n, B);
    prep_kernel<<<32, 256>>>(W1);
    init_kernel<<<(B + 255) / 256, 256>>>(B);
    score_kernel<<<(n + BM - 1) / BM, 256>>>(x, batch, b1, W2, n);
    seg_kernel<<<(n + 255) / 256, 256>>>(batch, n, B);
    pool_kernel<<<B, 256>>>(x, out, B);
}